// round 7
// baseline (speedup 1.0000x reference)
#include <cuda_runtime.h>
#include <math.h>

#define BS 1024
#define SL 512
#define TT 64
#define PD 4     // e/mask prefetch ring depth (steps)
#define WPB 4    // warps (=batches) per block

// Per-batch partials (static device globals: no allocation).
__device__ float g_score[BS];
__device__ float g_logZ[BS];
__device__ int   g_count[BS];

// ---- packed f32x2 helpers (PTX-only; ptxas won't auto-fuse) ----------------
__device__ __forceinline__ unsigned long long ffma2(unsigned long long a,
                                                    unsigned long long b,
                                                    unsigned long long c) {
    unsigned long long d;
    asm("fma.rn.f32x2 %0, %1, %2, %3;" : "=l"(d) : "l"(a), "l"(b), "l"(c));
    return d;
}
__device__ __forceinline__ unsigned long long addf2(unsigned long long a,
                                                    unsigned long long b) {
    unsigned long long d;
    asm("add.rn.f32x2 %0, %1, %2;" : "=l"(d) : "l"(a), "l"(b));
    return d;
}
__device__ __forceinline__ unsigned long long pack2(float x, float y) {
    unsigned long long r;
    asm("mov.b64 %0, {%1, %2};" : "=l"(r) : "f"(x), "f"(y));
    return r;
}
__device__ __forceinline__ void unpack2(unsigned long long v, float& lo, float& hi) {
    asm("mov.b64 {%0, %1}, %2;" : "=f"(lo), "=f"(hi) : "l"(v));
}
__device__ __forceinline__ float rcp_approx(float x) {
    float r;
    asm("rcp.approx.f32 %0, %1;" : "=f"(r) : "f"(x));
    return r;
}

// ---------------------------------------------------------------------------
// Score kernel: per-batch tag-path score + mask count.
// ---------------------------------------------------------------------------
__global__ void crf_score_kernel(const float* __restrict__ e,
                                 const int* __restrict__ tags,
                                 const unsigned char* __restrict__ mask,
                                 const float* __restrict__ st,
                                 const float* __restrict__ et,
                                 const float* __restrict__ t)
{
    const int b = blockIdx.x;
    const int tid = threadIdx.x;               // 128 threads
    const int* tg = tags + b * SL;
    const unsigned char* mk = mask + b * SL;
    const float* eb = e + (size_t)b * SL * TT;

    float s_local = 0.f;
    int c_local = 0;
    for (int s = tid; s < SL; s += 128) {
        int tag = tg[s];
        int m = mk[s] ? 1 : 0;
        if (s == 0) {
            s_local += st[tag] + eb[tag];
        } else if (m) {
            int tp = tg[s - 1];
            s_local += t[tp * TT + tag] + eb[(size_t)s * TT + tag];
        }
        c_local += m;
    }

    __shared__ float ssum[128];
    __shared__ int   scnt[128];
    ssum[tid] = s_local;
    scnt[tid] = c_local;
    __syncthreads();
    for (int off = 64; off > 0; off >>= 1) {
        if (tid < off) {
            ssum[tid] += ssum[tid + off];
            scnt[tid] += scnt[tid + off];
        }
        __syncthreads();
    }
    if (tid == 0) {
        float sc = ssum[0];
        int cnt = scnt[0];
        if (cnt > 0) sc += et[tg[cnt - 1]];
        g_score[b] = sc;
        g_count[b] = cnt;
    }
}

// ---------------------------------------------------------------------------
// Forward kernel: ONE WARP PER BATCH, 2 states per thread (lane l owns states
// 2l, 2l+1). The alpha vector lives in warp-private smem; per step:
//   STS.64 -> __syncwarp -> 16x LDS.128 broadcast -> 64x fma.f32x2.
// No __syncthreads at all (each warp fully independent -> all 4 SMSPs used,
// no cross-chain coupling). LDS instruction count per batch halved vs the
// 2-warp design (L1 was the busiest pipe at 54%).
// Linear-domain alpha, renormalized by a_prev[0]:
//   a_new[j] = (sum_i a[i]*P[i][j]) * exp(e[s][j]) * rcp(a0);  logb += log2(a0)
// ---------------------------------------------------------------------------
__global__ void __launch_bounds__(32 * WPB)
crf_forward_kernel(const float* __restrict__ e,
                   const unsigned char* __restrict__ mask,
                   const float* __restrict__ st,
                   const float* __restrict__ et,
                   const float* __restrict__ t)
{
    const int tid = threadIdx.x;
    const int w = tid >> 5;                    // warp in block = sub-batch
    const int l = tid & 31;                    // lane
    const int b = blockIdx.x * WPB + w;
    const int j0 = 2 * l;                      // owned states j0, j0+1

    __shared__ __align__(16) float a_sm[2][WPB][TT];

    // Packed P columns for states j0 and j0+1:
    //   P0[q] = (exp(t[2q][j0]),   exp(t[2q+1][j0]))
    //   P1[q] = (exp(t[2q][j0+1]), exp(t[2q+1][j0+1]))
    unsigned long long P0[TT / 2], P1[TT / 2];
#pragma unroll
    for (int q = 0; q < TT / 2; q++) {
        float2 ta = *(const float2*)&t[(2 * q + 0) * TT + j0];
        float2 tb = *(const float2*)&t[(2 * q + 1) * TT + j0];
        P0[q] = pack2(__expf(ta.x), __expf(tb.x));
        P1[q] = pack2(__expf(ta.y), __expf(tb.y));
    }

    const float* eb = e + (size_t)b * SL * TT;
    const unsigned char* mk = mask + b * SL;

    // Prefetch rings (slot s & (PD-1)).
    float2 er[PD];
    int    mring[PD];
#pragma unroll
    for (int i = 1; i <= PD; i++) {
        int ss = (i < SL) ? i : (SL - 1);
        er[i & (PD - 1)] = *(const float2*)&eb[(size_t)ss * TT + j0];
        mring[i & (PD - 1)] = mk[ss] ? 1 : 0;
    }

    // Step 0 init.
    float2 e0 = *(const float2*)&eb[j0];
    float ax = __expf(st[j0] + e0.x);
    float ay = __expf(st[j0 + 1] + e0.y);
    float logb = 0.f;

    int par = 0;
    *(float2*)&a_sm[0][w][j0] = make_float2(ax, ay);
    __syncwarp();

    float Ex = __expf(er[1 & (PD - 1)].x);     // exp(e[1][j0])
    float Ey = __expf(er[1 & (PD - 1)].y);

    for (int s0 = 1; s0 < SL; s0 += PD) {
#pragma unroll
        for (int k = 0; k < PD; k++) {
            const int s = s0 + k;
            if (s < SL) {
                const int p  = s & (PD - 1);
                const int pn = (s + 1) & (PD - 1);

                // Refill ring PD steps ahead (clamped; dead values unused).
                int sf = (s + PD < SL) ? (s + PD) : (SL - 1);
                float2 enew = *(const float2*)&eb[(size_t)sf * TT + j0];
                int    mnew = mk[sf] ? 1 : 0;

                int m = mring[p];

                // Renorm anchor (off critical path: overlaps the dot).
                float a0 = a_sm[par][w][0];
                float r  = rcp_approx(a0);
                float lg = __log2f(a0);

                const ulonglong2* av = (const ulonglong2*)(a_sm[par][w]);
                unsigned long long c0a = 0ull, c0b = 0ull;
                unsigned long long c1a = 0ull, c1b = 0ull;
#pragma unroll
                for (int q2 = 0; q2 < TT / 4; q2++) {
                    ulonglong2 v = av[q2];     // 4 alphas (2 packed pairs)
                    c0a = ffma2(v.x, P0[2 * q2 + 0], c0a);
                    c0b = ffma2(v.y, P0[2 * q2 + 1], c0b);
                    c1a = ffma2(v.x, P1[2 * q2 + 0], c1a);
                    c1b = ffma2(v.y, P1[2 * q2 + 1], c1b);
                }
                float s0lo, s0hi, s1lo, s1hi;
                unpack2(addf2(c0a, c0b), s0lo, s0hi);
                unpack2(addf2(c1a, c1b), s1lo, s1hi);
                float sum0 = s0lo + s0hi;
                float sum1 = s1lo + s1hi;

                if (m) {
                    ax = sum0 * (Ex * r);
                    ay = sum1 * (Ey * r);
                    logb += lg;
                }
                Ex = __expf(er[pn].x);         // exp(e[s+1]) off-path
                Ey = __expf(er[pn].y);
                er[p] = enew;
                mring[p] = mnew;

                par ^= 1;
                *(float2*)&a_sm[par][w][j0] = make_float2(ax, ay);
                __syncwarp();
            }
        }
    }

    // logZ = ln2*(logb + log2( sum_j a[j]*exp(et[j]) ))
    float2 etv = *(const float2*)&et[j0];
    float f = ax * __expf(etv.x) + ay * __expf(etv.y);
#pragma unroll
    for (int off = 16; off > 0; off >>= 1)
        f += __shfl_xor_sync(0xffffffffu, f, off);
    if (l == 0)
        g_logZ[b] = 0.69314718055994531f * (logb + __log2f(f));
}

// ---------------------------------------------------------------------------
// Deterministic final reduction: out = sum_b(score_b - logZ_b) / sum(mask)
// ---------------------------------------------------------------------------
__global__ void crf_finalize_kernel(float* __restrict__ out)
{
    const int tid = threadIdx.x;               // 256 threads
    float num = 0.f, tot = 0.f;
    for (int b = tid; b < BS; b += 256) {
        num += g_score[b] - g_logZ[b];
        tot += (float)g_count[b];
    }
    __shared__ float sn[256], stt[256];
    sn[tid] = num;
    stt[tid] = tot;
    __syncthreads();
    for (int off = 128; off > 0; off >>= 1) {
        if (tid < off) {
            sn[tid]  += sn[tid + off];
            stt[tid] += stt[tid + off];
        }
        __syncthreads();
    }
    if (tid == 0) out[0] = sn[0] / stt[0];
}

// ---------------------------------------------------------------------------
// Inputs (metadata order): e(f32), tags(i32), mask(bool->u8), st(f32),
// et(f32), t(f32). Output: single f32 scalar.
// ---------------------------------------------------------------------------
extern "C" void kernel_launch(void* const* d_in, const int* in_sizes, int n_in,
                              void* d_out, int out_size)
{
    const float*         e    = (const float*)d_in[0];
    const int*           tags = (const int*)d_in[1];
    const unsigned char* mask = (const unsigned char*)d_in[2];
    const float*         st   = (const float*)d_in[3];
    const float*         et   = (const float*)d_in[4];
    const float*         t    = (const float*)d_in[5];
    float* out = (float*)d_out;

    crf_forward_kernel<<<BS / WPB, 32 * WPB>>>(e, mask, st, et, t);
    crf_score_kernel<<<BS, 128>>>(e, tags, mask, st, et, t);
    crf_finalize_kernel<<<1, 256>>>(out);
}

// round 8
// speedup vs baseline: 1.6278x; 1.6278x over previous
#include <cuda_runtime.h>
#include <math.h>

#define BS 1024
#define SL 512
#define TT 64
#define RD 8     // e smem ring depth (steps); slot = s & (RD-1)

// Per-batch partials (static device globals: no allocation).
__device__ float g_score[BS];
__device__ float g_logZ[BS];
__device__ int   g_count[BS];

// ---- packed f32x2 helpers (PTX-only; ptxas won't auto-fuse) ----------------
__device__ __forceinline__ unsigned long long ffma2(unsigned long long a,
                                                    unsigned long long b,
                                                    unsigned long long c) {
    unsigned long long d;
    asm("fma.rn.f32x2 %0, %1, %2, %3;" : "=l"(d) : "l"(a), "l"(b), "l"(c));
    return d;
}
__device__ __forceinline__ unsigned long long addf2(unsigned long long a,
                                                    unsigned long long b) {
    unsigned long long d;
    asm("add.rn.f32x2 %0, %1, %2;" : "=l"(d) : "l"(a), "l"(b));
    return d;
}
__device__ __forceinline__ unsigned long long pack2(float x, float y) {
    unsigned long long r;
    asm("mov.b64 %0, {%1, %2};" : "=l"(r) : "f"(x), "f"(y));
    return r;
}
__device__ __forceinline__ void unpack2(unsigned long long v, float& lo, float& hi) {
    asm("mov.b64 {%0, %1}, %2;" : "=f"(lo), "=f"(hi) : "l"(v));
}
__device__ __forceinline__ float rcp_approx(float x) {
    float r;
    asm("rcp.approx.f32 %0, %1;" : "=f"(r) : "f"(x));
    return r;
}
// ---- cp.async: global->smem without touching registers ---------------------
__device__ __forceinline__ unsigned smem_u32(const void* p) {
    unsigned a;
    asm("{ .reg .u64 t; cvta.to.shared.u64 t, %1; cvt.u32.u64 %0, t; }"
        : "=r"(a) : "l"(p));
    return a;
}
__device__ __forceinline__ void cp_async4(unsigned dst, const void* src) {
    asm volatile("cp.async.ca.shared.global [%0], [%1], 4;"
                 :: "r"(dst), "l"(src) : "memory");
}
__device__ __forceinline__ void cp_commit() {
    asm volatile("cp.async.commit_group;" ::: "memory");
}
__device__ __forceinline__ void cp_wait6() {
    asm volatile("cp.async.wait_group 6;" ::: "memory");
}

// ---------------------------------------------------------------------------
// Score kernel: per-batch tag-path score + mask count.
// ---------------------------------------------------------------------------
__global__ void crf_score_kernel(const float* __restrict__ e,
                                 const int* __restrict__ tags,
                                 const unsigned char* __restrict__ mask,
                                 const float* __restrict__ st,
                                 const float* __restrict__ et,
                                 const float* __restrict__ t)
{
    const int b = blockIdx.x;
    const int tid = threadIdx.x;               // 128 threads
    const int* tg = tags + b * SL;
    const unsigned char* mk = mask + b * SL;
    const float* eb = e + (size_t)b * SL * TT;

    float s_local = 0.f;
    int c_local = 0;
    for (int s = tid; s < SL; s += 128) {
        int tag = tg[s];
        int m = mk[s] ? 1 : 0;
        if (s == 0) {
            s_local += st[tag] + eb[tag];
        } else if (m) {
            int tp = tg[s - 1];
            s_local += t[tp * TT + tag] + eb[(size_t)s * TT + tag];
        }
        c_local += m;
    }

    __shared__ float ssum[128];
    __shared__ int   scnt[128];
    ssum[tid] = s_local;
    scnt[tid] = c_local;
    __syncthreads();
    for (int off = 64; off > 0; off >>= 1) {
        if (tid < off) {
            ssum[tid] += ssum[tid + off];
            scnt[tid] += scnt[tid + off];
        }
        __syncthreads();
    }
    if (tid == 0) {
        float sc = ssum[0];
        int cnt = scnt[0];
        if (cnt > 0) sc += et[tg[cnt - 1]];
        g_score[b] = sc;
        g_count[b] = cnt;
    }
}

// ---------------------------------------------------------------------------
// Forward kernel: one 64-thread block per batch (best structure, R6).
// KEY CHANGE: the e-stream is staged global->smem via cp.async (no dest
// register -> no scoreboard stall). The old register ring materialized the
// LDG inside the issuing step, exposing ~1000cyc DRAM latency every step
// (step time was ~1000cyc in ALL prior variants). Mask is preloaded to smem
// once (512B), removing its per-step LDG entirely.
// Linear-domain alpha, renormalized by a_prev[0]:
//   a_new[j] = (sum_i a[i]*P[i][j]) * exp(e[s][j]) * rcp(a0);  logb += log2(a0)
// ---------------------------------------------------------------------------
__global__ void __launch_bounds__(TT)
crf_forward_kernel(const float* __restrict__ e,
                   const unsigned char* __restrict__ mask,
                   const float* __restrict__ st,
                   const float* __restrict__ et,
                   const float* __restrict__ t)
{
    const int b = blockIdx.x;
    const int j = threadIdx.x;                 // state index

    __shared__ __align__(16) float a_sm[2][TT];
    __shared__ __align__(16) float e_sm[RD][TT];
    __shared__ __align__(8)  unsigned char m_sm[SL];
    __shared__ float wred[2];

    // Packed P column: Pp[q] = { exp(t[2q][j]), exp(t[2q+1][j]) }
    unsigned long long Pp[TT / 2];
#pragma unroll
    for (int q = 0; q < TT / 2; q++) {
        float p0 = __expf(t[(2 * q + 0) * TT + j]);
        float p1 = __expf(t[(2 * q + 1) * TT + j]);
        Pp[q] = pack2(p0, p1);
    }

    const float* eb = e + (size_t)b * SL * TT;
    const unsigned char* mk = mask + b * SL;

    // Preload the whole mask row into smem (64 threads x 8B = 512B).
    ((unsigned long long*)m_sm)[j] = ((const unsigned long long*)mk)[j];

    // Prologue: start slices 1..RD in flight (one commit group per slice).
    const unsigned e_smem_base = smem_u32(&e_sm[0][0]);
#pragma unroll
    for (int i = 1; i <= RD; i++) {
        unsigned dst = e_smem_base + (((i & (RD - 1)) * TT + j) << 2);
        cp_async4(dst, &eb[(size_t)i * TT + j]);
        cp_commit();
    }

    float a = __expf(st[j] + eb[j]);           // linear alpha, step 0
    float logb = 0.f;

    int par = 0;
    a_sm[0][j] = a;
    __syncthreads();                           // a_sm + m_sm visible
    cp_wait6();                                // slices 1,2 ready
    float E = __expf(e_sm[1][j]);              // exp(e[1][j])
    int mcur = m_sm[1];

#pragma unroll 2
    for (int s = 1; s < SL; ++s) {
        // Keep the pipe full: issue slice s+RD into slot s&(RD-1).
        // (That slot's last reader — E for step s — finished at step s-1,
        //  before the barrier that ended it.)
        cp_wait6();                            // slices <= s+1 complete
        if (s + RD < SL) {
            unsigned dst = e_smem_base + (((s & (RD - 1)) * TT + j) << 2);
            cp_async4(dst, &eb[(size_t)(s + RD) * TT + j]);
        }
        cp_commit();                           // empty group OK near the end

        // Renorm anchor (off critical path: overlaps the dot).
        float a0 = a_sm[par][0];
        float r  = rcp_approx(a0);
        float lg = __log2f(a0);

        const ulonglong2* av = (const ulonglong2*)(a_sm[par]);
        unsigned long long acc0 = 0ull, acc1 = 0ull, acc2 = 0ull, acc3 = 0ull;
#pragma unroll
        for (int q2 = 0; q2 < TT / 4; q2++) {
            ulonglong2 v = av[q2];             // LDS.128 broadcast
            if (q2 & 1) {
                acc2 = ffma2(v.x, Pp[2 * q2 + 0], acc2);
                acc3 = ffma2(v.y, Pp[2 * q2 + 1], acc3);
            } else {
                acc0 = ffma2(v.x, Pp[2 * q2 + 0], acc0);
                acc1 = ffma2(v.y, Pp[2 * q2 + 1], acc1);
            }
        }
        unsigned long long sp = addf2(addf2(acc0, acc2), addf2(acc1, acc3));
        float slo, shi;
        unpack2(sp, slo, shi);
        float sum = slo + shi;

        if (mcur) {
            a = sum * (E * r);
            logb += lg;
        }

        // Next-step operands (slice s+1 guaranteed complete by the wait).
        int sn = (s + 1 < SL) ? (s + 1) : (SL - 1);
        E = __expf(e_sm[sn & (RD - 1)][j]);
        mcur = m_sm[sn];

        par ^= 1;
        a_sm[par][j] = a;
        __syncthreads();                       // one BAR per step
    }

    // logZ = ln2*(logb + log2( sum_j a[j]*exp(et[j]) ))
    float f = a * __expf(et[j]);
    const int lane = j & 31;
    const int wid = j >> 5;
#pragma unroll
    for (int off = 16; off > 0; off >>= 1)
        f += __shfl_xor_sync(0xffffffffu, f, off);
    if (lane == 0) wred[wid] = f;
    __syncthreads();
    if (j == 0) {
        float total = wred[0] + wred[1];
        g_logZ[b] = 0.69314718055994531f * (logb + __log2f(total));
    }
}

// ---------------------------------------------------------------------------
// Deterministic final reduction: out = sum_b(score_b - logZ_b) / sum(mask)
// ---------------------------------------------------------------------------
__global__ void crf_finalize_kernel(float* __restrict__ out)
{
    const int tid = threadIdx.x;               // 256 threads
    float num = 0.f, tot = 0.f;
    for (int b = tid; b < BS; b += 256) {
        num += g_score[b] - g_logZ[b];
        tot += (float)g_count[b];
    }
    __shared__ float sn[256], stt[256];
    sn[tid] = num;
    stt[tid] = tot;
    __syncthreads();
    for (int off = 128; off > 0; off >>= 1) {
        if (tid < off) {
            sn[tid]  += sn[tid + off];
            stt[tid] += stt[tid + off];
        }
        __syncthreads();
    }
    if (tid == 0) out[0] = sn[0] / stt[0];
}

// ---------------------------------------------------------------------------
// Inputs (metadata order): e(f32), tags(i32), mask(bool->u8), st(f32),
// et(f32), t(f32). Output: single f32 scalar.
// ---------------------------------------------------------------------------
extern "C" void kernel_launch(void* const* d_in, const int* in_sizes, int n_in,
                              void* d_out, int out_size)
{
    const float*         e    = (const float*)d_in[0];
    const int*           tags = (const int*)d_in[1];
    const unsigned char* mask = (const unsigned char*)d_in[2];
    const float*         st   = (const float*)d_in[3];
    const float*         et   = (const float*)d_in[4];
    const float*         t    = (const float*)d_in[5];
    float* out = (float*)d_out;

    crf_forward_kernel<<<BS, TT>>>(e, mask, st, et, t);
    crf_score_kernel<<<BS, 128>>>(e, tags, mask, st, et, t);
    crf_finalize_kernel<<<1, 256>>>(out);
}

// round 10
// speedup vs baseline: 1.9561x; 1.2017x over previous
#include <cuda_runtime.h>
#include <math.h>

#define BS 1024
#define SL 512
#define TT 64
#define RD 8     // e smem ring depth (steps); slot = s & (RD-1)
#define WPB 4    // warps per block = batches per block

// Per-batch partials (static device globals: no allocation).
__device__ float g_score[BS];
__device__ float g_logZ[BS];
__device__ int   g_count[BS];

// ---- packed f32x2 helpers (PTX-only; ptxas won't auto-fuse) ----------------
__device__ __forceinline__ unsigned long long ffma2(unsigned long long a,
                                                    unsigned long long b,
                                                    unsigned long long c) {
    unsigned long long d;
    asm("fma.rn.f32x2 %0, %1, %2, %3;" : "=l"(d) : "l"(a), "l"(b), "l"(c));
    return d;
}
__device__ __forceinline__ unsigned long long addf2(unsigned long long a,
                                                    unsigned long long b) {
    unsigned long long d;
    asm("add.rn.f32x2 %0, %1, %2;" : "=l"(d) : "l"(a), "l"(b));
    return d;
}
__device__ __forceinline__ unsigned long long pack2(float x, float y) {
    unsigned long long r;
    asm("mov.b64 %0, {%1, %2};" : "=l"(r) : "f"(x), "f"(y));
    return r;
}
__device__ __forceinline__ void unpack2(unsigned long long v, float& lo, float& hi) {
    asm("mov.b64 {%0, %1}, %2;" : "=f"(lo), "=f"(hi) : "l"(v));
}
__device__ __forceinline__ float rcp_approx(float x) {
    float r;
    asm("rcp.approx.f32 %0, %1;" : "=f"(r) : "f"(x));
    return r;
}
// ---- cp.async: global->smem without touching registers ---------------------
__device__ __forceinline__ unsigned smem_u32(const void* p) {
    unsigned a;
    asm("{ .reg .u64 t; cvta.to.shared.u64 t, %1; cvt.u32.u64 %0, t; }"
        : "=r"(a) : "l"(p));
    return a;
}
__device__ __forceinline__ void cp_async8(unsigned dst, const void* src) {
    asm volatile("cp.async.ca.shared.global [%0], [%1], 8;"
                 :: "r"(dst), "l"(src) : "memory");
}
__device__ __forceinline__ void cp_commit() {
    asm volatile("cp.async.commit_group;" ::: "memory");
}
__device__ __forceinline__ void cp_wait6() {
    asm volatile("cp.async.wait_group 6;" ::: "memory");
}

// ---------------------------------------------------------------------------
// Score kernel: per-batch tag-path score + mask count.
// ---------------------------------------------------------------------------
__global__ void crf_score_kernel(const float* __restrict__ e,
                                 const int* __restrict__ tags,
                                 const unsigned char* __restrict__ mask,
                                 const float* __restrict__ st,
                                 const float* __restrict__ et,
                                 const float* __restrict__ t)
{
    const int b = blockIdx.x;
    const int tid = threadIdx.x;               // 128 threads
    const int* tg = tags + b * SL;
    const unsigned char* mk = mask + b * SL;
    const float* eb = e + (size_t)b * SL * TT;

    float s_local = 0.f;
    int c_local = 0;
    for (int s = tid; s < SL; s += 128) {
        int tag = tg[s];
        int m = mk[s] ? 1 : 0;
        if (s == 0) {
            s_local += st[tag] + eb[tag];
        } else if (m) {
            int tp = tg[s - 1];
            s_local += t[tp * TT + tag] + eb[(size_t)s * TT + tag];
        }
        c_local += m;
    }

    __shared__ float ssum[128];
    __shared__ int   scnt[128];
    ssum[tid] = s_local;
    scnt[tid] = c_local;
    __syncthreads();
    for (int off = 64; off > 0; off >>= 1) {
        if (tid < off) {
            ssum[tid] += ssum[tid + off];
            scnt[tid] += scnt[tid + off];
        }
        __syncthreads();
    }
    if (tid == 0) {
        float sc = ssum[0];
        int cnt = scnt[0];
        if (cnt > 0) sc += et[tg[cnt - 1]];
        g_score[b] = sc;
        g_count[b] = cnt;
    }
}

// ---------------------------------------------------------------------------
// Forward kernel: ONE WARP PER BATCH, 2 states per thread (lane l owns states
// 2l, 2l+1); 4 independent warps per 128-thread block so wid%4 covers all 4
// SMSPs (R8's 2-warp blocks pinned everything to SMSP 0/1: issue=48.8% avg =
// ~97% on the active half; L1=74% from doubled broadcast LDS traffic).
// Per warp-step: STS.64 -> __syncwarp -> 16x LDS.128 -> 64x fma.f32x2.
// No __syncthreads anywhere in the loop; a0 renorm anchor via __shfl (lane 0).
// e staged via cp.async smem ring (R8 win); mask preloaded to smem per warp.
// Linear-domain alpha, renormalized by a_prev[0]:
//   a_new[j] = (sum_i a[i]*P[i][j]) * exp(e[s][j]) * rcp(a0);  logb += log2(a0)
// ---------------------------------------------------------------------------
__global__ void __launch_bounds__(32 * WPB)
crf_forward_kernel(const float* __restrict__ e,
                   const unsigned char* __restrict__ mask,
                   const float* __restrict__ st,
                   const float* __restrict__ et,
                   const float* __restrict__ t)
{
    const int tid = threadIdx.x;
    const int w = tid >> 5;                    // warp = sub-batch
    const int l = tid & 31;                    // lane
    const int b = blockIdx.x * WPB + w;
    const int j0 = 2 * l;                      // owned states j0, j0+1

    __shared__ __align__(16) float a_sm[WPB][2][TT];
    __shared__ __align__(16) float e_sm[WPB][RD][TT];
    __shared__ __align__(16) unsigned char m_sm[WPB][SL];

    // Packed P columns for states j0, j0+1:
    //   P0[q] = (exp(t[2q][j0]),   exp(t[2q+1][j0]))
    //   P1[q] = (exp(t[2q][j0+1]), exp(t[2q+1][j0+1]))
    unsigned long long P0[TT / 2], P1[TT / 2];
#pragma unroll
    for (int q = 0; q < TT / 2; q++) {
        float2 ta = *(const float2*)&t[(2 * q + 0) * TT + j0];
        float2 tb = *(const float2*)&t[(2 * q + 1) * TT + j0];
        P0[q] = pack2(__expf(ta.x), __expf(tb.x));
        P1[q] = pack2(__expf(ta.y), __expf(tb.y));
    }

    const float* eb = e + (size_t)b * SL * TT;
    const unsigned char* mk = mask + b * SL;

    // Preload mask row to smem (32 lanes x 16B).
    *(uint4*)&m_sm[w][l * 16] = *(const uint4*)&mk[l * 16];

    // Prologue: slices 1..RD in flight (one commit group per slice; 8B/lane).
    const unsigned e_base = smem_u32(&e_sm[w][0][0]);
#pragma unroll
    for (int i = 1; i <= RD; i++) {
        unsigned dst = e_base + (((i & (RD - 1)) * TT + j0) << 2);
        cp_async8(dst, &eb[(size_t)i * TT + j0]);
        cp_commit();
    }

    // Step 0 init.
    float2 e0 = *(const float2*)&eb[j0];
    float ax = __expf(st[j0] + e0.x);
    float ay = __expf(st[j0 + 1] + e0.y);
    float logb = 0.f;

    int par = 0;
    *(float2*)&a_sm[w][0][j0] = make_float2(ax, ay);
    __syncwarp();
    cp_wait6();                                // slices 1,2 ready
    {
        float2 ev = *(const float2*)&e_sm[w][1][j0];
        // carried exp(e) for the current step:
        // (Ex,Ey) recomputed at each step's end for s+1
        e0 = ev;
    }
    float Ex = __expf(e0.x);
    float Ey = __expf(e0.y);
    int mcur = m_sm[w][1];

    for (int s = 1; s < SL; ++s) {
        // Keep the pipe full: slices <= s+1 complete; issue slice s+RD.
        cp_wait6();
        if (s + RD < SL) {
            unsigned dst = e_base + (((s & (RD - 1)) * TT + j0) << 2);
            cp_async8(dst, &eb[(size_t)(s + RD) * TT + j0]);
        }
        cp_commit();

        // Renorm anchor from lane 0's register (no LDS).
        float a0 = __shfl_sync(0xffffffffu, ax, 0);
        float r  = rcp_approx(a0);
        float lg = __log2f(a0);

        const ulonglong2* av = (const ulonglong2*)(a_sm[w][par]);
        unsigned long long c0a = 0ull, c0b = 0ull;
        unsigned long long c1a = 0ull, c1b = 0ull;
#pragma unroll
        for (int q2 = 0; q2 < TT / 4; q2++) {
            ulonglong2 v = av[q2];             // LDS.128 broadcast: 4 alphas
            c0a = ffma2(v.x, P0[2 * q2 + 0], c0a);
            c0b = ffma2(v.y, P0[2 * q2 + 1], c0b);
            c1a = ffma2(v.x, P1[2 * q2 + 0], c1a);
            c1b = ffma2(v.y, P1[2 * q2 + 1], c1b);
        }
        float s0lo, s0hi, s1lo, s1hi;
        unpack2(addf2(c0a, c0b), s0lo, s0hi);
        unpack2(addf2(c1a, c1b), s1lo, s1hi);
        float sum0 = s0lo + s0hi;
        float sum1 = s1lo + s1hi;

        if (mcur) {
            ax = sum0 * (Ex * r);
            ay = sum1 * (Ey * r);
            logb += lg;
        }

        // Next-step operands (slice s+1 complete by the wait above).
        int sn = (s + 1 < SL) ? (s + 1) : (SL - 1);
        float2 ev = *(const float2*)&e_sm[w][sn & (RD - 1)][j0];
        Ex = __expf(ev.x);
        Ey = __expf(ev.y);
        mcur = m_sm[w][sn];

        par ^= 1;
        *(float2*)&a_sm[w][par][j0] = make_float2(ax, ay);
        __syncwarp();                          // warp-private; no BAR
    }

    // logZ = ln2*(logb + log2( sum_j a[j]*exp(et[j]) ))
    float2 etv = *(const float2*)&et[j0];
    float f = ax * __expf(etv.x) + ay * __expf(etv.y);
#pragma unroll
    for (int off = 16; off > 0; off >>= 1)
        f += __shfl_xor_sync(0xffffffffu, f, off);
    if (l == 0)
        g_logZ[b] = 0.69314718055994531f * (logb + __log2f(f));
}

// ---------------------------------------------------------------------------
// Deterministic final reduction: out = sum_b(score_b - logZ_b) / sum(mask)
// ---------------------------------------------------------------------------
__global__ void crf_finalize_kernel(float* __restrict__ out)
{
    const int tid = threadIdx.x;               // 256 threads
    float num = 0.f, tot = 0.f;
    for (int b = tid; b < BS; b += 256) {
        num += g_score[b] - g_logZ[b];
        tot += (float)g_count[b];
    }
    __shared__ float sn[256], stt[256];
    sn[tid] = num;
    stt[tid] = tot;
    __syncthreads();
    for (int off = 128; off > 0; off >>= 1) {
        if (tid < off) {
            sn[tid]  += sn[tid + off];
            stt[tid] += stt[tid + off];
        }
        __syncthreads();
    }
    if (tid == 0) out[0] = sn[0] / stt[0];
}

// ---------------------------------------------------------------------------
// Inputs (metadata order): e(f32), tags(i32), mask(bool->u8), st(f32),
// et(f32), t(f32). Output: single f32 scalar.
// ---------------------------------------------------------------------------
extern "C" void kernel_launch(void* const* d_in, const int* in_sizes, int n_in,
                              void* d_out, int out_size)
{
    const float*         e    = (const float*)d_in[0];
    const int*           tags = (const int*)d_in[1];
    const unsigned char* mask = (const unsigned char*)d_in[2];
    const float*         st   = (const float*)d_in[3];
    const float*         et   = (const float*)d_in[4];
    const float*         t    = (const float*)d_in[5];
    float* out = (float*)d_out;

    crf_forward_kernel<<<BS / WPB, 32 * WPB>>>(e, mask, st, et, t);
    crf_score_kernel<<<BS, 128>>>(e, tags, mask, st, et, t);
    crf_finalize_kernel<<<1, 256>>>(out);
}

// round 11
// speedup vs baseline: 2.0612x; 1.0537x over previous
#include <cuda_runtime.h>
#include <math.h>

#define BS 1024
#define SL 512
#define TT 64
#define RD 16    // e smem ring depth (slices); slot = s & 15
#define WPB 4    // warps per block
#define CH 64    // chunks of 4 steps per direction (256 steps each)

// Per-batch partials (static device globals: no allocation).
__device__ float g_score[BS];
__device__ float g_logZ[BS];
__device__ int   g_count[BS];
__device__ float g_alpha[BS][TT];   // forward half-state
__device__ float g_beta[BS][TT];    // backward half-state
__device__ float g_lbF[BS];
__device__ float g_lbB[BS];

// ---- packed f32x2 helpers (PTX-only; ptxas won't auto-fuse) ----------------
__device__ __forceinline__ unsigned long long ffma2(unsigned long long a,
                                                    unsigned long long b,
                                                    unsigned long long c) {
    unsigned long long d;
    asm("fma.rn.f32x2 %0, %1, %2, %3;" : "=l"(d) : "l"(a), "l"(b), "l"(c));
    return d;
}
__device__ __forceinline__ unsigned long long addf2(unsigned long long a,
                                                    unsigned long long b) {
    unsigned long long d;
    asm("add.rn.f32x2 %0, %1, %2;" : "=l"(d) : "l"(a), "l"(b));
    return d;
}
__device__ __forceinline__ unsigned long long pack2(float x, float y) {
    unsigned long long r;
    asm("mov.b64 %0, {%1, %2};" : "=l"(r) : "f"(x), "f"(y));
    return r;
}
__device__ __forceinline__ void unpack2(unsigned long long v, float& lo, float& hi) {
    asm("mov.b64 {%0, %1}, %2;" : "=f"(lo), "=f"(hi) : "l"(v));
}
__device__ __forceinline__ float rcp_approx(float x) {
    float r;
    asm("rcp.approx.f32 %0, %1;" : "=f"(r) : "f"(x));
    return r;
}
// ---- cp.async: global->smem without touching registers ---------------------
__device__ __forceinline__ unsigned smem_u32(const void* p) {
    unsigned a;
    asm("{ .reg .u64 t; cvta.to.shared.u64 t, %1; cvt.u32.u64 %0, t; }"
        : "=r"(a) : "l"(p));
    return a;
}
__device__ __forceinline__ void cp_async8(unsigned dst, const void* src) {
    asm volatile("cp.async.ca.shared.global [%0], [%1], 8;"
                 :: "r"(dst), "l"(src) : "memory");
}
__device__ __forceinline__ void cp_commit() {
    asm volatile("cp.async.commit_group;" ::: "memory");
}
__device__ __forceinline__ void cp_wait3() {
    asm volatile("cp.async.wait_group 3;" ::: "memory");
}

// ---------------------------------------------------------------------------
// Score kernel: per-batch tag-path score + mask count.
// ---------------------------------------------------------------------------
__global__ void crf_score_kernel(const float* __restrict__ e,
                                 const int* __restrict__ tags,
                                 const unsigned char* __restrict__ mask,
                                 const float* __restrict__ st,
                                 const float* __restrict__ et,
                                 const float* __restrict__ t)
{
    const int b = blockIdx.x;
    const int tid = threadIdx.x;               // 128 threads
    const int* tg = tags + b * SL;
    const unsigned char* mk = mask + b * SL;
    const float* eb = e + (size_t)b * SL * TT;

    float s_local = 0.f;
    int c_local = 0;
    for (int s = tid; s < SL; s += 128) {
        int tag = tg[s];
        int m = mk[s] ? 1 : 0;
        if (s == 0) {
            s_local += st[tag] + eb[tag];
        } else if (m) {
            int tp = tg[s - 1];
            s_local += t[tp * TT + tag] + eb[(size_t)s * TT + tag];
        }
        c_local += m;
    }

    __shared__ float ssum[128];
    __shared__ int   scnt[128];
    ssum[tid] = s_local;
    scnt[tid] = c_local;
    __syncthreads();
    for (int off = 64; off > 0; off >>= 1) {
        if (tid < off) {
            ssum[tid] += ssum[tid + off];
            scnt[tid] += scnt[tid + off];
        }
        __syncthreads();
    }
    if (tid == 0) {
        float sc = ssum[0];
        int cnt = scnt[0];
        if (cnt > 0) sc += et[tg[cnt - 1]];
        g_score[b] = sc;
        g_count[b] = cnt;
    }
}

// ---------------------------------------------------------------------------
// Forward-backward kernel. 2048 warps total: warp wg<1024 runs the FORWARD
// chain of batch wg (steps 1..256 -> alpha_256); warp wg>=1024 runs the
// BACKWARD chain of batch wg-1024 (beta <- P (E_s o beta), s = 511..257,
// plus one leading dummy masked step so both directions do 64 exact chunks
// of 4). This halves sequential depth and doubles warp count (occ 10.5% ->
// ~21%) — R10 showed nothing saturated (issue 41%, fma 38%, L1 47%), i.e.
// latency-bound on too few warps.
// Linear domain, renorm by lane0's value every 4 steps (worst-case growth
// between renorms ~1e31 < fp32 max). cp.async e-ring, one commit/wait per
// 4-step chunk. Final renorm flush keeps stored alpha/beta ~O(e^spread) so
// the combine dot cannot overflow.
// ---------------------------------------------------------------------------
__global__ void __launch_bounds__(32 * WPB)
crf_fb_kernel(const float* __restrict__ e,
              const unsigned char* __restrict__ mask,
              const float* __restrict__ st,
              const float* __restrict__ et,
              const float* __restrict__ t)
{
    const int tid = threadIdx.x;
    const int w = tid >> 5;
    const int l = tid & 31;
    const int wg = blockIdx.x * WPB + w;
    const int dir = wg >> 10;                  // 0 = forward, 1 = backward
    const int b = wg & (BS - 1);
    const int j0 = 2 * l;                      // owned states j0, j0+1

    __shared__ __align__(16) float a_sm[WPB][2][TT];
    __shared__ __align__(16) float e_sm[WPB][RD][TT];
    __shared__ __align__(16) unsigned char m_sm[WPB][SL];

    const float* eb = e + (size_t)b * SL * TT;
    const unsigned char* mk = mask + b * SL;

    // Mask row to smem (32 lanes x 16B).
    *(uint4*)&m_sm[w][l * 16] = *(const uint4*)&mk[l * 16];

    // P operand, packed over i-pairs. Forward needs COLUMNS j0/j0+1 of
    // P[i][j]=exp(t[i][j]); backward needs ROWS j0/j0+1 (transpose recursion).
    unsigned long long Pa[TT / 2], Pb[TT / 2];
    if (dir == 0) {
#pragma unroll
        for (int q = 0; q < TT / 2; q++) {
            float2 ta = *(const float2*)&t[(2 * q + 0) * TT + j0];
            float2 tb = *(const float2*)&t[(2 * q + 1) * TT + j0];
            Pa[q] = pack2(__expf(ta.x), __expf(tb.x));
            Pb[q] = pack2(__expf(ta.y), __expf(tb.y));
        }
    } else {
#pragma unroll
        for (int q = 0; q < TT / 2; q++) {
            float2 ra = *(const float2*)&t[(j0 + 0) * TT + 2 * q];
            float2 rb = *(const float2*)&t[(j0 + 1) * TT + 2 * q];
            Pa[q] = pack2(__expf(ra.x), __expf(ra.y));
            Pb[q] = pack2(__expf(rb.x), __expf(rb.y));
        }
    }

    const unsigned e_base = smem_u32(&e_sm[w][0][0]);
    float ax, ay;                              // alpha (fwd) / beta (bwd)
    float logb = 0.f;
    int par = 0;

    if (dir == 0) {
        // Prologue: slices 1..16 in 4 groups of 4.
#pragma unroll
        for (int i = 1; i <= 16; i++) {
            cp_async8(e_base + (((i & 15) * TT + j0) << 2),
                      &eb[(size_t)i * TT + j0]);
            if ((i & 3) == 0) cp_commit();
        }
        float2 e0 = *(const float2*)&eb[j0];
        ax = __expf(st[j0] + e0.x);
        ay = __expf(st[j0 + 1] + e0.y);

        for (int c = 0; c < CH; c++) {
            cp_wait3();                        // slices 4c+1..4c+4 ready
#pragma unroll
            for (int k = 0; k < 4; k++) {
                const int s = 4 * c + 1 + k;
                par ^= 1;
                *(float2*)&a_sm[w][par][j0] = make_float2(ax, ay);
                __syncwarp();

                float2 ev = *(const float2*)&e_sm[w][s & 15][j0];
                int m = m_sm[w][s];

                const ulonglong2* av = (const ulonglong2*)(a_sm[w][par]);
                unsigned long long c0a = 0ull, c0b = 0ull;
                unsigned long long c1a = 0ull, c1b = 0ull;
#pragma unroll
                for (int q2 = 0; q2 < TT / 4; q2++) {
                    ulonglong2 v = av[q2];
                    c0a = ffma2(v.x, Pa[2 * q2 + 0], c0a);
                    c0b = ffma2(v.y, Pa[2 * q2 + 1], c0b);
                    c1a = ffma2(v.x, Pb[2 * q2 + 0], c1a);
                    c1b = ffma2(v.y, Pb[2 * q2 + 1], c1b);
                }
                float s0lo, s0hi, s1lo, s1hi;
                unpack2(addf2(c0a, c0b), s0lo, s0hi);
                unpack2(addf2(c1a, c1b), s1lo, s1hi);
                float nx = (s0lo + s0hi) * __expf(ev.x);
                float ny = (s1lo + s1hi) * __expf(ev.y);
                ax = m ? nx : ax;
                ay = m ? ny : ay;

                if (k == 3) {                  // renorm every 4 steps
                    float a0 = __shfl_sync(0xffffffffu, ax, 0);
                    float r = rcp_approx(a0);
                    ax *= r; ay *= r;
                    logb += __log2f(a0);
                }
            }
            // Refill the 4 just-freed slots with slices 4c+17..4c+20.
            int sf = 4 * c + 17;
#pragma unroll
            for (int i = 0; i < 4; i++) {
                int sl = sf + i;
                if (sl <= 4 * CH)
                    cp_async8(e_base + (((sl & 15) * TT + j0) << 2),
                              &eb[(size_t)sl * TT + j0]);
            }
            cp_commit();
        }
        *(float2*)&g_alpha[b][j0] = make_float2(ax, ay);
        if (l == 0) g_lbF[b] = logb;
    } else {
        // Prologue: slices 511,510,509 | 508..505 | 504..501 | 500..497.
#pragma unroll
        for (int i = 0; i < 3; i++) {
            int sl = 511 - i;
            cp_async8(e_base + (((sl & 15) * TT + j0) << 2),
                      &eb[(size_t)sl * TT + j0]);
        }
        cp_commit();
#pragma unroll
        for (int gi = 0; gi < 12; gi++) {
            int sl = 508 - gi;
            cp_async8(e_base + (((sl & 15) * TT + j0) << 2),
                      &eb[(size_t)sl * TT + j0]);
            if ((gi & 3) == 3) cp_commit();
        }
        ax = __expf(et[j0]);
        ay = __expf(et[j0 + 1]);

        for (int c = 0; c < CH; c++) {
            cp_wait3();
#pragma unroll
            for (int k = 0; k < 4; k++) {
                const int s = 512 - 4 * c - k;  // c=0: 512(dummy),511,510,509
                const int si = (s > 511) ? 511 : s;
                int m = (s > 511) ? 0 : m_sm[w][si];

                float2 ev = *(const float2*)&e_sm[w][si & 15][j0];
                float gx = __expf(ev.x) * ax;  // g = E_s o beta
                float gy = __expf(ev.y) * ay;
                par ^= 1;
                *(float2*)&a_sm[w][par][j0] = make_float2(gx, gy);
                __syncwarp();

                const ulonglong2* av = (const ulonglong2*)(a_sm[w][par]);
                unsigned long long c0a = 0ull, c0b = 0ull;
                unsigned long long c1a = 0ull, c1b = 0ull;
#pragma unroll
                for (int q2 = 0; q2 < TT / 4; q2++) {
                    ulonglong2 v = av[q2];
                    c0a = ffma2(v.x, Pa[2 * q2 + 0], c0a);
                    c0b = ffma2(v.y, Pa[2 * q2 + 1], c0b);
                    c1a = ffma2(v.x, Pb[2 * q2 + 0], c1a);
                    c1b = ffma2(v.y, Pb[2 * q2 + 1], c1b);
                }
                float s0lo, s0hi, s1lo, s1hi;
                unpack2(addf2(c0a, c0b), s0lo, s0hi);
                unpack2(addf2(c1a, c1b), s1lo, s1hi);
                float nx = s0lo + s0hi;
                float ny = s1lo + s1hi;
                ax = m ? nx : ax;
                ay = m ? ny : ay;

                if (k == 3) {
                    float a0 = __shfl_sync(0xffffffffu, ax, 0);
                    float r = rcp_approx(a0);
                    ax *= r; ay *= r;
                    logb += __log2f(a0);
                }
            }
            // Refill slices 496-4c .. 493-4c (needed by chunk c+4).
            int sf = 496 - 4 * c;
#pragma unroll
            for (int i = 0; i < 4; i++) {
                int sl = sf - i;
                if (sl >= 257)
                    cp_async8(e_base + (((sl & 15) * TT + j0) << 2),
                              &eb[(size_t)sl * TT + j0]);
            }
            cp_commit();
        }
        *(float2*)&g_beta[b][j0] = make_float2(ax, ay);
        if (l == 0) g_lbB[b] = logb;
    }
}

// ---------------------------------------------------------------------------
// Combine: logZ_b = ln2 * (lbF + lbB + log2( dot(alpha_b, beta_b) )).
// One warp per batch.
// ---------------------------------------------------------------------------
__global__ void crf_combine_kernel()
{
    const int warp = (blockIdx.x * blockDim.x + threadIdx.x) >> 5;
    const int l = threadIdx.x & 31;
    if (warp >= BS) return;
    float2 av = *(const float2*)&g_alpha[warp][2 * l];
    float2 bv = *(const float2*)&g_beta[warp][2 * l];
    float d = av.x * bv.x + av.y * bv.y;
#pragma unroll
    for (int off = 16; off > 0; off >>= 1)
        d += __shfl_xor_sync(0xffffffffu, d, off);
    if (l == 0)
        g_logZ[warp] = 0.69314718055994531f *
                       (g_lbF[warp] + g_lbB[warp] + __log2f(d));
}

// ---------------------------------------------------------------------------
// Deterministic final reduction: out = sum_b(score_b - logZ_b) / sum(mask)
// ---------------------------------------------------------------------------
__global__ void crf_finalize_kernel(float* __restrict__ out)
{
    const int tid = threadIdx.x;               // 256 threads
    float num = 0.f, tot = 0.f;
    for (int b = tid; b < BS; b += 256) {
        num += g_score[b] - g_logZ[b];
        tot += (float)g_count[b];
    }
    __shared__ float sn[256], stt[256];
    sn[tid] = num;
    stt[tid] = tot;
    __syncthreads();
    for (int off = 128; off > 0; off >>= 1) {
        if (tid < off) {
            sn[tid]  += sn[tid + off];
            stt[tid] += stt[tid + off];
        }
        __syncthreads();
    }
    if (tid == 0) out[0] = sn[0] / stt[0];
}

// ---------------------------------------------------------------------------
// Inputs (metadata order): e(f32), tags(i32), mask(bool->u8), st(f32),
// et(f32), t(f32). Output: single f32 scalar.
// ---------------------------------------------------------------------------
extern "C" void kernel_launch(void* const* d_in, const int* in_sizes, int n_in,
                              void* d_out, int out_size)
{
    const float*         e    = (const float*)d_in[0];
    const int*           tags = (const int*)d_in[1];
    const unsigned char* mask = (const unsigned char*)d_in[2];
    const float*         st   = (const float*)d_in[3];
    const float*         et   = (const float*)d_in[4];
    const float*         t    = (const float*)d_in[5];
    float* out = (float*)d_out;

    crf_fb_kernel<<<(2 * BS) / WPB, 32 * WPB>>>(e, mask, st, et, t);
    crf_score_kernel<<<BS, 128>>>(e, tags, mask, st, et, t);
    crf_combine_kernel<<<BS / 8, 256>>>();
    crf_finalize_kernel<<<1, 256>>>(out);
}